// round 9
// baseline (speedup 1.0000x reference)
#include <cuda_runtime.h>
#include <cuda_bf16.h>
#include <stdint.h>
#include <math.h>

// ---------------- problem constants ----------------
#define NNODES 50000
#define NKEEP  320000
#define D_IN   128
#define D_OUT  256
#define D_HID  512
#define BN_EPS 1e-5f
#define YBLK   391                    // row blocks per pass
#define PADN   (YBLK * 128)           // 50048 padded rows per pass

typedef __nv_bfloat16 bf16;
typedef __nv_bfloat162 bf162;

__device__ __forceinline__ uint32_t packbf(float a, float b) {
    bf162 t = __floats2bfloat162_rn(a, b);
    return *(uint32_t*)&t;
}

// ---------------- device scratch (stacked [2*PADN, C], bf16 hot buffers) ------
__device__ bf16  g_agg [(size_t)2 * PADN * D_OUT];
__device__ bf16  g_T   [(size_t)2 * PADN * D_HID];
__device__ bf16  g_V   [(size_t)2 * PADN * D_OUT];
__device__ float g_REX [(size_t)2 * PADN * D_IN];
__device__ bf16  g_wb[655360];
__device__ int   g_src1[NKEEP], g_dst1[NKEEP], g_src2[NKEEP], g_dst2[NKEEP];
__device__ unsigned char g_mA[NNODES], g_mB[NNODES];
__device__ float g_stats[2048];            // [half][ sum(512) | sq(512) ]
__device__ float g_sc1[2 * D_HID], g_sh1[2 * D_HID];
__device__ float g_sc2[2 * D_HID], g_sh2[2 * D_HID];
__device__ float g_acc[8];
__device__ int   g_flags[2];

// ---------------- detection (also zeroes accumulators each replay) ------------
__global__ void detect_k(const int* __restrict__ e1w, const unsigned char* __restrict__ m1b) {
    if (threadIdx.x == 0 && blockIdx.x == 0) {
        int nz = 0;
        for (int i = 0; i < 64; ++i) nz += (e1w[2 * i + 1] != 0);
        g_flags[0] = (nz == 0) ? 1 : 0;
        int nzb = 0;
        for (int i = 0; i < 256; ++i) if (i & 3) nzb += (m1b[i] != 0);
        g_flags[1] = (nzb == 0) ? 1 : 0;
        for (int i = 0; i < 8; ++i) g_acc[i] = 0.f;
    }
}

// both passes in one launch: blockIdx.y selects pass
__global__ void prep_k(const int* __restrict__ e1, const int* __restrict__ e2,
                       int* __restrict__ src1, int* __restrict__ dst1,
                       int* __restrict__ src2, int* __restrict__ dst2,
                       const void* __restrict__ m1, const void* __restrict__ m2,
                       unsigned char* __restrict__ mA, unsigned char* __restrict__ mB,
                       float* __restrict__ acc) {
    int pass = blockIdx.y;
    const int* eraw = pass ? e2 : e1;
    int* src = pass ? src2 : src1;
    int* dst = pass ? dst2 : dst1;
    const void* mraw = pass ? m2 : m1;
    unsigned char* m = pass ? mB : mA;
    float* cnt = acc + 3 + pass;
    int e = blockIdx.x * 256 + threadIdx.x;
    if (e < NKEEP) {
        if (g_flags[0]) { src[e] = eraw[2 * e]; dst[e] = eraw[2 * (NKEEP + e)]; }
        else            { src[e] = eraw[e];     dst[e] = eraw[NKEEP + e]; }
    }
    if ((int)blockIdx.x * 256 < NNODES) {
        unsigned char v = 0;
        if (e < NNODES) {
            if (g_flags[1]) v = (((const unsigned int*)mraw)[e] != 0u);
            else            v = (((const unsigned char*)mraw)[e] != 0);
            m[e] = v;
        }
        __shared__ int s[256];
        s[threadIdx.x] = v;
        __syncthreads();
        for (int o = 128; o; o >>= 1) {
            if (threadIdx.x < o) s[threadIdx.x] += s[threadIdx.x + o];
            __syncthreads();
        }
        if (threadIdx.x == 0) atomicAdd(cnt, (float)s[0]);
    }
}

// all 6 weight conversions in one launch (blockIdx.y = segment)
__global__ void convw_k(const float* w0, const float* w1, const float* w2,
                        const float* w3, const float* w4, const float* w5,
                        bf16* __restrict__ dst) {
    const int  sizes[6] = {65536, 131072, 131072, 131072, 131072, 65536};
    const int  offs [6] = {0, 65536, 196608, 327680, 458752, 589824};
    int seg = blockIdx.y;
    const float* srcs[6] = {w0, w1, w2, w3, w4, w5};
    int i = blockIdx.x * 256 + threadIdx.x;
    if (i < sizes[seg]) dst[offs[seg] + i] = __float2bfloat16_rn(srcs[seg][i]);
}

// ---------------- elementwise ----------------
// agg(bf16)[both halves] = where(mask,0,x); pairs of columns
__global__ void maskagg_k(const float* __restrict__ X, bf16* __restrict__ AGG,
                          const unsigned char* __restrict__ mA, const unsigned char* __restrict__ mB) {
    size_t i = (size_t)blockIdx.x * blockDim.x + threadIdx.x;
    const size_t hp = (size_t)NNODES * 64;          // pairs per half (D_IN/2)
    if (i >= 2 * hp) return;
    int pass = i >= hp;
    size_t j = i - (pass ? hp : 0);
    int row = (int)(j >> 6);
    float2 f = ((const float2*)X)[j];
    if ((pass ? mB : mA)[row]) { f.x = 0.f; f.y = 0.f; }
    ((bf162*)AGG)[j + (size_t)pass * PADN * 64] = __floats2bfloat162_rn(f.x, f.y);
}

// agg(bf16) = relu(V*sc+sh), optional per-pass row mask; bf162 pairs
template <bool MASK>
__global__ void postbn_k(const bf16* __restrict__ V, bf16* __restrict__ OUT,
                         const float* __restrict__ sc, const float* __restrict__ sh,
                         const unsigned char* __restrict__ mA, const unsigned char* __restrict__ mB) {
    size_t i = (size_t)blockIdx.x * blockDim.x + threadIdx.x;
    const size_t hp = (size_t)NNODES * 128;         // pairs per half (D_OUT/2)
    if (i >= 2 * hp) return;
    int pass = i >= hp;
    size_t j = i - (pass ? hp : 0);
    int c2 = (int)(j & 127) * 2;
    size_t vi = j + (size_t)pass * PADN * 128;
    float2 f = __bfloat1622float2(((const bf162*)V)[vi]);
    int k0 = pass * 512 + c2;
    f.x = fmaxf(f.x * sc[k0] + sh[k0], 0.f);
    f.y = fmaxf(f.y * sc[k0 + 1] + sh[k0 + 1], 0.f);
    if (MASK) {
        int row = (int)(j >> 7);
        if ((pass ? mB : mA)[row]) { f.x = 0.f; f.y = 0.f; }
    }
    ((bf162*)OUT)[vi] = __floats2bfloat162_rn(f.x, f.y);
}

// ---------------- merged scatter-add (both passes, bf16 atomics) --------------
// layer-0: fp32 x gather, masked source skip, v2.bf16x2 red (D_IN)
__global__ void scatterf_k(const float* __restrict__ X, bf16* __restrict__ AGG,
                           const int* __restrict__ s1, const int* __restrict__ d1,
                           const int* __restrict__ s2, const int* __restrict__ d2,
                           const unsigned char* __restrict__ mA, const unsigned char* __restrict__ mB) {
    int slot = blockIdx.x * blockDim.y + threadIdx.y;
    if (slot >= 2 * NKEEP) return;
    int pass = slot >= NKEEP;
    int e = slot - (pass ? NKEEP : 0);
    int s = pass ? s2[e] : s1[e];
    if ((pass ? mB : mA)[s]) return;
    int d = pass ? d2[e] : d1[e];
    int c = threadIdx.x;                         // 0..31, 4 floats each
    float4 v = ((const float4*)X)[(size_t)s * 32 + c];
    uint32_t h0 = packbf(v.x, v.y), h1 = packbf(v.z, v.w);
    bf16* p = AGG + ((size_t)(pass ? PADN : 0) + d) * D_IN + c * 4;
    asm volatile("red.global.add.noftz.v2.bf16x2 [%0], {%1,%2};"
                 :: "l"(p), "r"(h0), "r"(h1) : "memory");
}

// layers 1/2: bf16 V gather with BN+relu; v4.bf16x2 red (D_OUT)
template <bool MASK>
__global__ void scatterb_k(const bf16* __restrict__ V, bf16* __restrict__ AGG,
                           const int* __restrict__ s1, const int* __restrict__ d1,
                           const int* __restrict__ s2, const int* __restrict__ d2,
                           const float* __restrict__ sc, const float* __restrict__ sh,
                           const unsigned char* __restrict__ mA, const unsigned char* __restrict__ mB) {
    int slot = blockIdx.x * blockDim.y + threadIdx.y;
    if (slot >= 2 * NKEEP) return;
    int pass = slot >= NKEEP;
    int e = slot - (pass ? NKEEP : 0);
    int s = pass ? s2[e] : s1[e];
    if (MASK && (pass ? mB : mA)[s]) return;
    int d = pass ? d2[e] : d1[e];
    int c = threadIdx.x;                         // 0..31, 8 bf16 each
    size_t base = (size_t)(pass ? PADN : 0);
    uint4 raw = ((const uint4*)V)[(base + s) * 32 + c];
    const bf162* hh = (const bf162*)&raw;
    int k0 = pass * 512 + c * 8;
    uint32_t h[4];
#pragma unroll
    for (int j = 0; j < 4; ++j) {
        float2 f = __bfloat1622float2(hh[j]);
        f.x = fmaxf(f.x * sc[k0 + 2 * j]     + sh[k0 + 2 * j],     0.f);
        f.y = fmaxf(f.y * sc[k0 + 2 * j + 1] + sh[k0 + 2 * j + 1], 0.f);
        h[j] = packbf(f.x, f.y);
    }
    bf16* p = AGG + (base + d) * D_OUT + c * 8;
    asm volatile("red.global.add.noftz.v4.bf16x2 [%0], {%1,%2,%3,%4};"
                 :: "l"(p), "r"(h[0]), "r"(h[1]), "r"(h[2]), "r"(h[3]) : "memory");
}

// ---------------- BN scale/shift, both halves (reads stats, re-zeroes) --------
__global__ void scaleshift_k(float* __restrict__ stats,
                             const float* __restrict__ g, const float* __restrict__ b,
                             float* __restrict__ sc, float* __restrict__ sh, int C) {
    int idx = blockIdx.x * blockDim.x + threadIdx.x;
    if (idx >= 2 * C) return;
    int half = idx >= C;
    int c = idx - (half ? C : 0);
    float* st = stats + half * 1024;
    const float invN = 1.f / (float)NNODES;
    float s_ = st[c], q_ = st[512 + c];
    st[c] = 0.f; st[512 + c] = 0.f;
    float mu  = s_ * invN;
    float var = q_ * invN - mu * mu;
    float rs  = rsqrtf(var + BN_EPS);
    float s   = g[c] * rs;
    sc[half * 512 + c] = s;
    sh[half * 512 + c] = b[c] - mu * s;
}

// ---------------- bf16 GEMM, bf16 A and C, stacked halves, fused stats --------
// C[2*PADN,Ncol] = A'[2*PADN,K] @ W[K,Ncol]; TA: A'=relu(A*sc+sh) at smem store.
template <bool TA>
__global__ void __launch_bounds__(256, 2)
bgemm_k(const bf16* __restrict__ A, const bf16* __restrict__ W, bf16* __restrict__ C,
        int K, int Ncol, const float* __restrict__ sc, const float* __restrict__ sh,
        float* __restrict__ stats) {
    __shared__ __align__(16) bf16 As[2][128][40];
    __shared__ __align__(16) bf16 Bs[2][32][136];
    __shared__ float s_sum[128], s_sq[128];
    const int tid  = threadIdx.x;
    const int wid  = tid >> 5, lane = tid & 31;
    const int warpM = wid & 1, warpN = wid >> 1;
    const int half = blockIdx.y >= YBLK;
    const int by = blockIdx.y * 128, bx = blockIdx.x * 128;
    const int lby = by - half * PADN;
    const float* scp = sc + half * 512;
    const float* shp = sh + half * 512;
    float* st = stats + half * 1024;
    const int lq = lane >> 2, lr = lane & 3;
    const int arH = tid >> 2, acH = (tid & 3) * 8;   // bf16 A-load: 8 elems/thread, 2 its
    const int bkr = tid >> 4, bc = (tid & 15) * 8;
    const int brow = lane & 15;
    const int aRow = (lane & 7) + ((lane >> 3) & 1) * 8;
    const int aKh  = (lane >> 4) * 8;

    const uint32_t bsBase = (uint32_t)__cvta_generic_to_shared(&Bs[0][0][0]);
    const uint32_t asBase = (uint32_t)__cvta_generic_to_shared(&As[0][0][0]);

    float acc[4][4][4] = {};
    uint4  aReg[2];
    uint4  bReg[2];
    const int nT = K >> 5;

#define LOADA(kb)                                                                     \
    _Pragma("unroll")                                                                 \
    for (int it = 0; it < 2; ++it)                                                    \
        aReg[it] = *(const uint4*)(A + (size_t)(by + arH + it * 64) * K + (kb) + acH);

#define STOREA(buf, kb)                                                               \
    _Pragma("unroll")                                                                 \
    for (int it = 0; it < 2; ++it) {                                                  \
        if (!TA) {                                                                    \
            const uint2* u = (const uint2*)&aReg[it];                                 \
            *(uint2*)&As[buf][arH + it * 64][acH]     = u[0];                         \
            *(uint2*)&As[buf][arH + it * 64][acH + 4] = u[1];                         \
        } else {                                                                      \
            const bf162* hh = (const bf162*)&aReg[it];                                \
            int k0 = (kb) + acH;                                                      \
            bool dead = (lby + arH + it * 64) >= NNODES;                              \
            _Pragma("unroll")                                                         \
            for (int j = 0; j < 4; ++j) {                                             \
                float2 f = __bfloat1622float2(hh[j]);                                 \
                f.x = fmaxf(f.x * scp[k0 + 2 * j]     + shp[k0 + 2 * j],     0.f);    \
                f.y = fmaxf(f.y * scp[k0 + 2 * j + 1] + shp[k0 + 2 * j + 1], 0.f);    \
                if (dead) { f.x = 0.f; f.y = 0.f; }                                   \
                *(bf162*)&As[buf][arH + it * 64][acH + 2 * j] = __floats2bfloat162_rn(f.x, f.y); \
            }                                                                         \
        }                                                                             \
    }

    // ---- tile 0 ----
    LOADA(0)
#pragma unroll
    for (int it = 0; it < 2; ++it)
        bReg[it] = *(const uint4*)(W + (size_t)(bkr + it * 16) * Ncol + bx + bc);
    STOREA(0, 0)
#pragma unroll
    for (int it = 0; it < 2; ++it)
        *(uint4*)&Bs[0][bkr + it * 16][bc] = bReg[it];
    __syncthreads();

    for (int t = 0; t < nT; ++t) {
        const int buf = t & 1;
        if (t + 1 < nT) {
            const int kb = (t + 1) * 32;
            LOADA(kb)
#pragma unroll
            for (int it = 0; it < 2; ++it)
                bReg[it] = *(const uint4*)(W + (size_t)(kb + bkr + it * 16) * Ncol + bx + bc);
        }

#pragma unroll
        for (int k16 = 0; k16 < 2; ++k16) {
            const int kk = k16 * 16;
            uint32_t af[4][4], bf[4][2];
#pragma unroll
            for (int mt = 0; mt < 4; ++mt) {
                int rm = warpM * 64 + mt * 16;
                uint32_t addr = asBase + (uint32_t)(((buf * 128 + rm + aRow) * 40 + kk + aKh) * 2);
                asm volatile("ldmatrix.sync.aligned.m8n8.x4.shared.b16 {%0,%1,%2,%3}, [%4];"
                             : "=r"(af[mt][0]), "=r"(af[mt][1]), "=r"(af[mt][2]), "=r"(af[mt][3])
                             : "r"(addr));
            }
#pragma unroll
            for (int nt = 0; nt < 4; ++nt) {
                int cn = warpN * 32 + nt * 8;
                uint32_t addr = bsBase + (uint32_t)(((buf * 32 + kk + brow) * 136 + cn) * 2);
                asm volatile("ldmatrix.sync.aligned.m8n8.x2.trans.shared.b16 {%0,%1}, [%2];"
                             : "=r"(bf[nt][0]), "=r"(bf[nt][1]) : "r"(addr));
            }
#pragma unroll
            for (int mt = 0; mt < 4; ++mt)
#pragma unroll
                for (int nt = 0; nt < 4; ++nt) {
                    asm volatile(
                        "mma.sync.aligned.m16n8k16.row.col.f32.bf16.bf16.f32 "
                        "{%0,%1,%2,%3}, {%4,%5,%6,%7}, {%8,%9}, {%0,%1,%2,%3};"
                        : "+f"(acc[mt][nt][0]), "+f"(acc[mt][nt][1]),
                          "+f"(acc[mt][nt][2]), "+f"(acc[mt][nt][3])
                        : "r"(af[mt][0]), "r"(af[mt][1]), "r"(af[mt][2]), "r"(af[mt][3]),
                          "r"(bf[nt][0]), "r"(bf[nt][1]));
                }
        }

        if (t + 1 < nT) {
            const int nb = buf ^ 1;
            const int kb = (t + 1) * 32;
            STOREA(nb, kb)
#pragma unroll
            for (int it = 0; it < 2; ++it)
                *(uint4*)&Bs[nb][bkr + it * 16][bc] = bReg[it];
            __syncthreads();
        }
    }

    // ---- store C (bf16, padded buffer: unconditional) ----
#pragma unroll
    for (int mt = 0; mt < 4; ++mt) {
        int r0 = by + warpM * 64 + mt * 16 + lq;
        int r1 = r0 + 8;
#pragma unroll
        for (int nt = 0; nt < 4; ++nt) {
            int c0 = bx + warpN * 32 + nt * 8 + lr * 2;
            *(bf162*)(C + (size_t)r0 * Ncol + c0) = __floats2bfloat162_rn(acc[mt][nt][0], acc[mt][nt][1]);
            *(bf162*)(C + (size_t)r1 * Ncol + c0) = __floats2bfloat162_rn(acc[mt][nt][2], acc[mt][nt][3]);
        }
    }

    // ---- fused BN stats (per half); pad rows contribute exact zeros ----
    for (int i = tid; i < 128; i += 256) { s_sum[i] = 0.f; s_sq[i] = 0.f; }
    __syncthreads();
#pragma unroll
    for (int nt = 0; nt < 4; ++nt) {
        float s0 = 0.f, q0 = 0.f, s1 = 0.f, q1 = 0.f;
#pragma unroll
        for (int mt = 0; mt < 4; ++mt) {
            float a0 = acc[mt][nt][0], a1 = acc[mt][nt][1];
            float a2 = acc[mt][nt][2], a3 = acc[mt][nt][3];
            s0 += a0 + a2; q0 += a0 * a0 + a2 * a2;
            s1 += a1 + a3; q1 += a1 * a1 + a3 * a3;
        }
#pragma unroll
        for (int o = 4; o < 32; o <<= 1) {
            s0 += __shfl_xor_sync(0xffffffffu, s0, o);
            q0 += __shfl_xor_sync(0xffffffffu, q0, o);
            s1 += __shfl_xor_sync(0xffffffffu, s1, o);
            q1 += __shfl_xor_sync(0xffffffffu, q1, o);
        }
        if (lq == 0) {
            int c0 = warpN * 32 + nt * 8 + lr * 2;
            atomicAdd(&s_sum[c0],     s0); atomicAdd(&s_sq[c0],     q0);
            atomicAdd(&s_sum[c0 + 1], s1); atomicAdd(&s_sq[c0 + 1], q1);
        }
    }
    __syncthreads();
    for (int i = tid; i < 128; i += 256) {
        atomicAdd(&st[bx + i],       s_sum[i]);
        atomicAdd(&st[512 + bx + i], s_sq[i]);
    }
#undef LOADA
#undef STOREA
}

// ---------------- decoder postbn + masked cosine loss, fused (warp/row) -------
__global__ void pbnloss_k(const bf16* __restrict__ V, float* __restrict__ REX,
                          const float* __restrict__ X,
                          const float* __restrict__ sc, const float* __restrict__ sh,
                          const unsigned char* __restrict__ mA, const unsigned char* __restrict__ mB,
                          float* __restrict__ acc) {
    int warp = threadIdx.x >> 5, lane = threadIdx.x & 31;
    int gr = blockIdx.x * 8 + warp;
    __shared__ float s_loss[2];
    if (threadIdx.x < 2) s_loss[threadIdx.x] = 0.f;
    __syncthreads();
    if (gr < 2 * NNODES) {
        int pass = gr >= NNODES;
        int r = gr - (pass ? NNODES : 0);
        size_t rowIdx = (size_t)(pass ? PADN : 0) + r;
        uint2 raw = ((const uint2*)(V + rowIdx * D_IN))[lane];
        const bf162* hh = (const bf162*)&raw;
        float2 f0 = __bfloat1622float2(hh[0]);
        float2 f1 = __bfloat1622float2(hh[1]);
        int k0 = pass * 512 + lane * 4;
        float4 a;
        a.x = fmaxf(f0.x * sc[k0 + 0] + sh[k0 + 0], 0.f);
        a.y = fmaxf(f0.y * sc[k0 + 1] + sh[k0 + 1], 0.f);
        a.z = fmaxf(f1.x * sc[k0 + 2] + sh[k0 + 2], 0.f);
        a.w = fmaxf(f1.y * sc[k0 + 3] + sh[k0 + 3], 0.f);
        ((float4*)(REX + rowIdx * D_IN))[lane] = a;
        float4 b = ((const float4*)(X + (size_t)r * D_IN))[lane];
        float dot = a.x * b.x + a.y * b.y + a.z * b.z + a.w * b.w;
        float na  = a.x * a.x + a.y * a.y + a.z * a.z + a.w * a.w;
        float nb  = b.x * b.x + b.y * b.y + b.z * b.z + b.w * b.w;
#pragma unroll
        for (int o = 16; o; o >>= 1) {
            dot += __shfl_down_sync(0xffffffffu, dot, o);
            na  += __shfl_down_sync(0xffffffffu, na , o);
            nb  += __shfl_down_sync(0xffffffffu, nb , o);
        }
        if (lane == 0 && (pass ? mB : mA)[r]) {
            float c = dot / (fmaxf(sqrtf(na), 1e-12f) * fmaxf(sqrtf(nb), 1e-12f));
            atomicAdd(&s_loss[pass], 1.f - c);
        }
    }
    __syncthreads();
    if (threadIdx.x < 2) {
        float t = s_loss[threadIdx.x];
        if (t != 0.f) atomicAdd(&acc[threadIdx.x], t);
    }
}

// ---------------- contrastive loss: cos(REX2, REX1) ----------------
__global__ void cl_k(const float* __restrict__ REX, float* __restrict__ acc) {
    int warp = threadIdx.x >> 5, lane = threadIdx.x & 31;
    int row = blockIdx.x * 8 + warp;
    float contrib = 0.f;
    if (row < NNODES) {
        float4 a = ((const float4*)(REX + (size_t)row * D_IN))[lane];
        float4 b = ((const float4*)(REX + ((size_t)PADN + row) * D_IN))[lane];
        float dot = a.x * b.x + a.y * b.y + a.z * b.z + a.w * b.w;
        float na  = a.x * a.x + a.y * a.y + a.z * a.z + a.w * a.w;
        float nb  = b.x * b.x + b.y * b.y + b.z * b.z + b.w * b.w;
#pragma unroll
        for (int o = 16; o; o >>= 1) {
            dot += __shfl_down_sync(0xffffffffu, dot, o);
            na  += __shfl_down_sync(0xffffffffu, na , o);
            nb  += __shfl_down_sync(0xffffffffu, nb , o);
        }
        if (lane == 0) {
            float c = dot / (fmaxf(sqrtf(na), 1e-12f) * fmaxf(sqrtf(nb), 1e-12f));
            contrib = 1.f - c;
        }
    }
    __shared__ float s[8];
    if (lane == 0) s[warp] = contrib;
    __syncthreads();
    if (threadIdx.x == 0) {
        float t = 0.f;
#pragma unroll
        for (int j = 0; j < 8; ++j) t += s[j];
        atomicAdd(acc, t);
    }
}

__global__ void final_k(float* __restrict__ out) {
    out[0] = g_acc[0] / g_acc[3] + g_acc[1] / g_acc[4] + 0.1f * (g_acc[2] / (float)NNODES);
}

extern "C" void kernel_launch(void* const* d_in, const int* in_sizes, int n_in,
                              void* d_out, int out_size) {
    const float* x = (const float*)d_in[0];
    const int* e1raw = (const int*)d_in[1];
    const int* e2raw = (const int*)d_in[2];
    const unsigned char* m1raw = (const unsigned char*)d_in[3];
    const unsigned char* m2raw = (const unsigned char*)d_in[4];
    const float* e0_w1 = (const float*)d_in[6];
    const float* e0_w2 = (const float*)d_in[7];
    const float* e0_bg = (const float*)d_in[8];
    const float* e0_bb = (const float*)d_in[9];
    const float* e0_ng = (const float*)d_in[10];
    const float* e0_nb = (const float*)d_in[11];
    const float* e1_w1 = (const float*)d_in[12];
    const float* e1_w2 = (const float*)d_in[13];
    const float* e1_bg = (const float*)d_in[14];
    const float* e1_bb = (const float*)d_in[15];
    const float* e1_ng = (const float*)d_in[16];
    const float* e1_nb = (const float*)d_in[17];
    const float* dw1   = (const float*)d_in[18];
    const float* dw2   = (const float*)d_in[19];
    const float* dbg   = (const float*)d_in[20];
    const float* dbb   = (const float*)d_in[21];
    const float* dng   = (const float*)d_in[22];
    const float* dnb   = (const float*)d_in[23];
    float* out = (float*)d_out;

    float *p_REX, *p_stats, *p_sc1, *p_sh1, *p_sc2, *p_sh2, *p_acc;
    bf16 *p_agg, *p_T, *p_V, *p_wb;
    int *p_src1, *p_dst1, *p_src2, *p_dst2;
    unsigned char *p_mA, *p_mB;
    cudaGetSymbolAddress((void**)&p_agg,  g_agg);
    cudaGetSymbolAddress((void**)&p_T,    g_T);
    cudaGetSymbolAddress((void**)&p_V,    g_V);
    cudaGetSymbolAddress((void**)&p_REX,  g_REX);
    cudaGetSymbolAddress((void**)&p_stats,g_stats);
    cudaGetSymbolAddress((void**)&p_sc1,  g_sc1);
    cudaGetSymbolAddress((void**)&p_sh1,  g_sh1);
    cudaGetSymbolAddress((void**)&p_sc2,  g_sc2);
    cudaGetSymbolAddress((void**)&p_sh2,  g_sh2);
    cudaGetSymbolAddress((void**)&p_acc,  g_acc);
    cudaGetSymbolAddress((void**)&p_src1, g_src1);
    cudaGetSymbolAddress((void**)&p_dst1, g_dst1);
    cudaGetSymbolAddress((void**)&p_src2, g_src2);
    cudaGetSymbolAddress((void**)&p_dst2, g_dst2);
    cudaGetSymbolAddress((void**)&p_mA,   g_mA);
    cudaGetSymbolAddress((void**)&p_mB,   g_mB);
    cudaGetSymbolAddress((void**)&p_wb,   g_wb);

    bf16* wb_e0w1 = p_wb + 0;
    bf16* wb_e0w2 = p_wb + 65536;
    bf16* wb_e1w1 = p_wb + 196608;
    bf16* wb_e1w2 = p_wb + 327680;
    bf16* wb_dw1  = p_wb + 458752;
    bf16* wb_dw2  = p_wb + 589824;

    const unsigned EB = (NKEEP + 255) / 256;
    const unsigned sgf = (2 * NKEEP + 7) / 8;
    const unsigned sgb = (2 * NKEEP + 3) / 4;
    const unsigned maG = (unsigned)((2 * (size_t)NNODES * 64 + 255) / 256);
    const unsigned pbG = (unsigned)((2 * (size_t)NNODES * 128 + 255) / 256);

    // ---- launch order: #5 is the first bgemm (ncu -s 5 -c 1 profiles it) ----
    detect_k<<<1, 32>>>(e1raw, m1raw);                                               // 0
    prep_k<<<dim3(EB, 2), 256>>>(e1raw, e2raw, p_src1, p_dst1, p_src2, p_dst2,
                                 m1raw, m2raw, p_mA, p_mB, p_acc);                   // 1
    convw_k<<<dim3(512, 6), 256>>>(e0_w1, e0_w2, e1_w1, e1_w2, dw1, dw2, p_wb);      // 2
    maskagg_k<<<maG, 256>>>(x, p_agg, p_mA, p_mB);                                   // 3
    scatterf_k<<<sgf, dim3(32, 8)>>>(x, p_agg, p_src1, p_dst1, p_src2, p_dst2, p_mA, p_mB); // 4
    bgemm_k<false><<<dim3(4, 2 * YBLK), 256>>>(p_agg, wb_e0w1, p_T, D_IN, D_HID, nullptr, nullptr, p_stats); // 5
    scaleshift_k<<<4, 256>>>(p_stats, e0_bg, e0_bb, p_sc1, p_sh1, D_HID);
    bgemm_k<true><<<dim3(2, 2 * YBLK), 256>>>(p_T, wb_e0w2, p_V, D_HID, D_OUT, p_sc1, p_sh1, p_stats);
    scaleshift_k<<<2, 256>>>(p_stats, e0_ng, e0_nb, p_sc2, p_sh2, D_OUT);
    postbn_k<false><<<pbG, 256>>>(p_V, p_agg, p_sc2, p_sh2, p_mA, p_mB);

    // ---- encoder layer 1 ----
    scatterb_k<false><<<sgb, dim3(32, 8)>>>(p_V, p_agg, p_src1, p_dst1, p_src2, p_dst2, p_sc2, p_sh2, p_mA, p_mB);
    bgemm_k<false><<<dim3(4, 2 * YBLK), 256>>>(p_agg, wb_e1w1, p_T, D_OUT, D_HID, nullptr, nullptr, p_stats);
    scaleshift_k<<<4, 256>>>(p_stats, e1_bg, e1_bb, p_sc1, p_sh1, D_HID);
    bgemm_k<true><<<dim3(2, 2 * YBLK), 256>>>(p_T, wb_e1w2, p_V, D_HID, D_OUT, p_sc1, p_sh1, p_stats);
    scaleshift_k<<<2, 256>>>(p_stats, e1_ng, e1_nb, p_sc2, p_sh2, D_OUT);
    postbn_k<true><<<pbG, 256>>>(p_V, p_agg, p_sc2, p_sh2, p_mA, p_mB);   // re_h mask

    // ---- decoder ----
    scatterb_k<true><<<sgb, dim3(32, 8)>>>(p_V, p_agg, p_src1, p_dst1, p_src2, p_dst2, p_sc2, p_sh2, p_mA, p_mB);
    bgemm_k<false><<<dim3(4, 2 * YBLK), 256>>>(p_agg, wb_dw1, p_T, D_OUT, D_HID, nullptr, nullptr, p_stats);
    scaleshift_k<<<4, 256>>>(p_stats, dbg, dbb, p_sc1, p_sh1, D_HID);
    bgemm_k<true><<<dim3(1, 2 * YBLK), 256>>>(p_T, wb_dw2, p_V, D_HID, D_IN, p_sc1, p_sh1, p_stats);
    scaleshift_k<<<1, 256>>>(p_stats, dng, dnb, p_sc2, p_sh2, D_IN);

    pbnloss_k<<<(2 * NNODES + 7) / 8, 256>>>(p_V, p_REX, x, p_sc2, p_sh2, p_mA, p_mB, p_acc);
    cl_k<<<(NNODES + 7) / 8, 256>>>(p_REX, p_acc + 2);
    final_k<<<1, 1>>>(out);
    (void)in_sizes; (void)n_in; (void)out_size;
}